// round 15
// baseline (speedup 1.0000x reference)
#include <cuda_runtime.h>
#include <cuda_bf16.h>
#include <math.h>

// Problem constants
#define Bc 2
#define Tc 2048
#define Dc 1024
#define Hc 16
#define DHc 64
#define Rc 32
#define TDc (3*Dc)        // 3072
#define Mrows (Bc*Tc)     // 4096
#define LRW 2048          // combined row: [ql(512) | kl(512) | v(1024)]

// Scratch (device globals — no allocation allowed)
__device__ float g_wc[(size_t)Dc*LRW];        // folded weights (tf32-rounded)
__device__ float g_lr[(size_t)Mrows*LRW];     // [ql | kl | v] per row (tf32-rounded by GEMM1 epilogue)
__device__ float g_y [(size_t)Mrows*Dc];      // attention output (fp32)

__device__ __forceinline__ float cvt_tf32(float x) {
    float r;
    asm("cvt.rna.tf32.f32 %0, %1;" : "=f"(r) : "f"(x));
    return r;
}

__device__ __forceinline__ void mma_tf32(float* c, const unsigned* a, const unsigned* b) {
    asm volatile(
        "mma.sync.aligned.m16n8k8.row.col.f32.tf32.tf32.f32 "
        "{%0,%1,%2,%3},{%4,%5,%6,%7},{%8,%9},{%0,%1,%2,%3};"
        : "+f"(c[0]), "+f"(c[1]), "+f"(c[2]), "+f"(c[3])
        : "r"(a[0]), "r"(a[1]), "r"(a[2]), "r"(a[3]), "r"(b[0]), "r"(b[1]));
}

__device__ __forceinline__ void cp16(void* smem, const void* gmem) {
    unsigned saddr = (unsigned)__cvta_generic_to_shared(smem);
    asm volatile("cp.async.ca.shared.global [%0], [%1], 16;" :: "r"(saddr), "l"(gmem));
}
__device__ __forceinline__ void cp_commit() {
    asm volatile("cp.async.commit_group;");
}
template<int N>
__device__ __forceinline__ void cp_wait() {
    asm volatile("cp.async.wait_group %0;" :: "n"(N));
}

// ---------------------------------------------------------------------------
// Weight folding + V copy merged (z=0: fold q/k LSR; z=1: copy V weights).
// ---------------------------------------------------------------------------
__global__ __launch_bounds__(256) void prep_kernel(const float* __restrict__ Wqkv,
                                                   const float* __restrict__ Wql,
                                                   const float* __restrict__ Wkl,
                                                   const float* __restrict__ core,
                                                   float* __restrict__ wc) {
    if (blockIdx.z == 1) {
        const int id = blockIdx.y * 8 + blockIdx.x;   // 0..127
        const int tid = threadIdx.x;
#pragma unroll
        for (int rr = 0; rr < 8; rr++) {
            const int row = id * 8 + rr;
            const int c = tid * 4;
            float4 v = *reinterpret_cast<const float4*>(&Wqkv[(size_t)row*TDc + 2*Dc + c]);
            v.x = cvt_tf32(v.x); v.y = cvt_tf32(v.y);
            v.z = cvt_tf32(v.z); v.w = cvt_tf32(v.w);
            *reinterpret_cast<float4*>(&wc[(size_t)row*LRW + 1024 + c]) = v;
        }
        return;
    }

    const int h  = blockIdx.y;
    const int d0 = blockIdx.x * 128;
    __shared__ float Wq[DHc*Rc], Wk[DHc*Rc];
    __shared__ float Aq[32*DHc], Ak[32*DHc];
    __shared__ float cs[Rc];
    const int tid = threadIdx.x;
    for (int i = tid; i < DHc*Rc; i += 256) {
        Wq[i] = Wql[(size_t)h*DHc*Rc + i];
        Wk[i] = Wkl[(size_t)h*DHc*Rc + i];
    }
    if (tid < Rc) cs[tid] = core[h*Rc + tid] * 0.17677669529663687f;
    __syncthreads();

    for (int c = 0; c < 4; c++) {
        const int dbase = d0 + c*32;
        for (int f = tid; f < 512; f += 256) {
            const int row = f >> 4, cc = (f & 15) << 2;
            float4 va = *reinterpret_cast<const float4*>(&Wqkv[(size_t)(dbase+row)*TDc + h*DHc + cc]);
            *reinterpret_cast<float4*>(&Aq[row*DHc + cc]) = va;
            float4 vb = *reinterpret_cast<const float4*>(&Wqkv[(size_t)(dbase+row)*TDc + Dc + h*DHc + cc]);
            *reinterpret_cast<float4*>(&Ak[row*DHc + cc]) = vb;
        }
        __syncthreads();
        const int r = tid & 31, i0 = tid >> 5;
#pragma unroll
        for (int ii = 0; ii < 4; ii++) {
            const int i = i0*4 + ii;
            float sq = 0.f, sk = 0.f;
#pragma unroll
            for (int dh = 0; dh < DHc; dh++) {
                sq = fmaf(Aq[i*DHc + dh], Wq[dh*Rc + r], sq);
                sk = fmaf(Ak[i*DHc + dh], Wk[dh*Rc + r], sk);
            }
            wc[(size_t)(dbase+i)*LRW + h*Rc + r]       = cvt_tf32(sq * cs[r]);
            wc[(size_t)(dbase+i)*LRW + 512 + h*Rc + r] = cvt_tf32(sk);
        }
        __syncthreads();
    }
}

// ---------------------------------------------------------------------------
// TF32 tensor-core GEMM (unchanged proven config).
// ---------------------------------------------------------------------------
template<bool ROUNDC>
__global__ __launch_bounds__(256, 2) void gemm_tf32_kernel(const float* __restrict__ A,
                                                           const float* __restrict__ B,
                                                           float* __restrict__ C,
                                                           int M, int N, int K, int ldb) {
    __shared__ __align__(16) float As[2][128][20];
    __shared__ __align__(16) float Bs[2][16][136];

    const int tid = threadIdx.x;
    const int warp = tid >> 5, lane = tid & 31;
    const int g = lane >> 2, tig = lane & 3;
    const int wm = warp >> 2;
    const int wn = warp & 3;

    const int c0 = tid * 2;
    const int aRow0 = c0 >> 2,       aKc0 = (c0 & 3) << 2;
    const int aRow1 = (c0+1) >> 2,   aKc1 = ((c0+1) & 3) << 2;
    const int bKr0 = c0 >> 5,        bNc0 = (c0 & 31) << 2;
    const int bKr1 = (c0+1) >> 5,    bNc1 = ((c0+1) & 31) << 2;

    const float* Ab = A + (size_t)blockIdx.y * 128 * K;
    const float* Bb = B + (size_t)blockIdx.x * 128;

    float acc[4][4][4];
#pragma unroll
    for (int i = 0; i < 4; i++)
#pragma unroll
        for (int j = 0; j < 4; j++)
#pragma unroll
            for (int e = 0; e < 4; e++) acc[i][j][e] = 0.f;

    const int nK = K >> 4;

    cp16(&As[0][aRow0][aKc0], &Ab[(size_t)aRow0 * K + aKc0]);
    cp16(&As[0][aRow1][aKc1], &Ab[(size_t)aRow1 * K + aKc1]);
    cp16(&Bs[0][bKr0][bNc0], &Bb[(size_t)bKr0 * ldb + bNc0]);
    cp16(&Bs[0][bKr1][bNc1], &Bb[(size_t)bKr1 * ldb + bNc1]);
    cp_commit();

    int buf = 0;
    for (int kt = 0; kt < nK; kt++) {
        const bool more = (kt + 1 < nK);
        if (more) {
            const int k0 = (kt + 1) << 4;
            const int nb = buf ^ 1;
            cp16(&As[nb][aRow0][aKc0], &Ab[(size_t)aRow0 * K + k0 + aKc0]);
            cp16(&As[nb][aRow1][aKc1], &Ab[(size_t)aRow1 * K + k0 + aKc1]);
            cp16(&Bs[nb][bKr0][bNc0], &Bb[(size_t)(k0 + bKr0) * ldb + bNc0]);
            cp16(&Bs[nb][bKr1][bNc1], &Bb[(size_t)(k0 + bKr1) * ldb + bNc1]);
            cp_commit();
            cp_wait<1>();
        } else {
            cp_wait<0>();
        }
        __syncthreads();

#pragma unroll
        for (int ks = 0; ks < 16; ks += 8) {
            unsigned afr[4][4], bfr[4][2];
#pragma unroll
            for (int im = 0; im < 4; im++) {
                const int m0 = wm * 64 + im * 16;
                afr[im][0] = __float_as_uint(cvt_tf32(As[buf][m0 + g     ][ks + tig    ]));
                afr[im][1] = __float_as_uint(cvt_tf32(As[buf][m0 + g + 8 ][ks + tig    ]));
                afr[im][2] = __float_as_uint(cvt_tf32(As[buf][m0 + g     ][ks + tig + 4]));
                afr[im][3] = __float_as_uint(cvt_tf32(As[buf][m0 + g + 8 ][ks + tig + 4]));
            }
#pragma unroll
            for (int in_ = 0; in_ < 4; in_++) {
                const int n0 = wn * 32 + in_ * 8;
                bfr[in_][0] = __float_as_uint(cvt_tf32(Bs[buf][ks + tig    ][n0 + g]));
                bfr[in_][1] = __float_as_uint(cvt_tf32(Bs[buf][ks + tig + 4][n0 + g]));
            }
#pragma unroll
            for (int im = 0; im < 4; im++)
#pragma unroll
                for (int in_ = 0; in_ < 4; in_++)
                    mma_tf32(acc[im][in_], afr[im], bfr[in_]);
        }
        __syncthreads();
        buf ^= 1;
    }

#pragma unroll
    for (int im = 0; im < 4; im++) {
        const size_t row0 = (size_t)blockIdx.y * 128 + wm * 64 + im * 16 + g;
#pragma unroll
        for (int in_ = 0; in_ < 4; in_++) {
            const size_t col = (size_t)blockIdx.x * 128 + wn * 32 + in_ * 8 + tig * 2;
            float2 v0, v1;
            if (ROUNDC) {
                v0 = make_float2(cvt_tf32(acc[im][in_][0]), cvt_tf32(acc[im][in_][1]));
                v1 = make_float2(cvt_tf32(acc[im][in_][2]), cvt_tf32(acc[im][in_][3]));
            } else {
                v0 = make_float2(acc[im][in_][0], acc[im][in_][1]);
                v1 = make_float2(acc[im][in_][2], acc[im][in_][3]);
            }
            *reinterpret_cast<float2*>(&C[row0 * N + col])       = v0;
            *reinterpret_cast<float2*>(&C[(row0 + 8) * N + col]) = v1;
        }
    }
}

// ---------------------------------------------------------------------------
// Tensor-core flash attention: 512 threads (16 warps), 256 q-rows per block,
// 64-key cp.async double-buffered tiles — halves per-tile overhead per query.
// No online softmax (fixed max=0); p fp32; operands pre-rounded by GEMM1.
// ---------------------------------------------------------------------------
#define KLS_STRIDE 36
#define VS_STRIDE  72
#define KT 64
#define KLS_TILE (KT*KLS_STRIDE)   // 2304 floats
#define VS_TILE  (KT*VS_STRIDE)    // 4608 floats
#define ATTN_SMEM ((2*(KLS_TILE + VS_TILE)) * 4)   // 55296 B

__global__ __launch_bounds__(512, 1) void attn_tc_kernel(float* __restrict__ y) {
    extern __shared__ __align__(16) float asm_[];
    float* klsB = asm_;                  // [2][64][36]
    float* vsB  = asm_ + 2*KLS_TILE;     // [2][64][72]

    const int blk = blockIdx.x;
    const int q0 = 7 - (blk & 7);        // 256-row q-tile, heavy first
    const int h  = (blk >> 3) & 15;
    const int b  = blk >> 7;
    const int tid  = threadIdx.x;
    const int warp = tid >> 5, lane = tid & 31;
    const int g = lane >> 2, tig = lane & 3;
    const int m0 = warp * 16;            // 0..240 within the 256-row block

    const float* klg = g_lr + (size_t)(b*Tc) * LRW + 512 + h*Rc;
    const float* vg  = g_lr + (size_t)(b*Tc) * LRW + 1024 + h*DHc;

    // preload ql A-fragments (already tf32-rounded in memory)
    unsigned aq[4][4];
    {
        const float* qlp = g_lr + (size_t)(b*Tc + q0*256 + m0) * LRW + h*Rc;
#pragma unroll
        for (int ks = 0; ks < 4; ks++) {
            aq[ks][0] = __float_as_uint(qlp[(size_t)(g    )*LRW + ks*8 + tig    ]);
            aq[ks][1] = __float_as_uint(qlp[(size_t)(g + 8)*LRW + ks*8 + tig    ]);
            aq[ks][2] = __float_as_uint(qlp[(size_t)(g    )*LRW + ks*8 + tig + 4]);
            aq[ks][3] = __float_as_uint(qlp[(size_t)(g + 8)*LRW + ks*8 + tig + 4]);
        }
    }

    float of[8][4];
#pragma unroll
    for (int nt = 0; nt < 8; nt++)
#pragma unroll
        for (int e = 0; e < 4; e++) of[nt][e] = 0.f;
    float l0 = 0.f, l1 = 0.f;

    const unsigned srcA = (lane & ~3u) | (unsigned)(tig >> 1);
    const unsigned srcB = srcA + 2u;

    // 512 threads: 1 kl float4 + 2 v float4 per thread per tile
#define ATT_COPY(s, kt)                                                                   \
    do {                                                                                  \
        float* kls_ = klsB + (s)*KLS_TILE;                                                \
        float* vs_  = vsB  + (s)*VS_TILE;                                                 \
        {                                                                                 \
            const int f = tid;                                                            \
            const int key = f >> 3, r0 = (f & 7) << 2;                                    \
            cp16(&kls_[key*KLS_STRIDE + r0], klg + (size_t)((kt)*KT + key)*LRW + r0);     \
        }                                                                                 \
        _Pragma("unroll")                                                                 \
        for (int i = 0; i < 2; i++) {                                                     \
            const int f = tid + i*512;                                                    \
            const int key = f >> 4, j = (f & 15) << 2;                                    \
            cp16(&vs_[key*VS_STRIDE + j], vg + (size_t)((kt)*KT + key)*LRW + j);          \
        }                                                                                 \
        cp_commit();                                                                      \
    } while (0)

    const int ktMax = 4*q0 + 3;          // inclusive; block covers rows [256q0, 256q0+256)
    ATT_COPY(0, 0);

    int buf = 0;
    for (int kt = 0; kt <= ktMax; kt++) {
        if (kt < ktMax) {
            ATT_COPY(buf ^ 1, kt + 1);
            cp_wait<1>();
        } else {
            cp_wait<0>();
        }
        __syncthreads();   // tile kt visible in slot buf

        const bool masked = (kt >= 4*q0);
        const int cbase = (kt - 4*q0) * KT;       // local column base (vs block row 0)
        const bool skip = masked && ((m0 + 15) < cbase);

        if (!skip) {
            const float* kls = klsB + buf*KLS_TILE;
            const float* vs  = vsB  + buf*VS_TILE;

            // S = ql @ kl^T  (16 x 64)
            float sf[8][4];
#pragma unroll
            for (int nt = 0; nt < 8; nt++) {
#pragma unroll
                for (int e = 0; e < 4; e++) sf[nt][e] = 0.f;
#pragma unroll
                for (int ks = 0; ks < 4; ks++) {
                    unsigned bb[2];
                    bb[0] = __float_as_uint(kls[(nt*8 + g)*KLS_STRIDE + ks*8 + tig    ]);
                    bb[1] = __float_as_uint(kls[(nt*8 + g)*KLS_STRIDE + ks*8 + tig + 4]);
                    mma_tf32(sf[nt], aq[ks], bb);
                }
            }

            if (masked) {
                const int r0l = m0 + g, r1l = r0l + 8;
#pragma unroll
                for (int nt = 0; nt < 8; nt++) {
                    const int c = cbase + nt*8 + 2*tig;
                    if (c     > r0l) sf[nt][0] = -1e30f;
                    if (c + 1 > r0l) sf[nt][1] = -1e30f;
                    if (c     > r1l) sf[nt][2] = -1e30f;
                    if (c + 1 > r1l) sf[nt][3] = -1e30f;
                }
            }

            // p = exp(s) (fixed max 0); fp32 p feeds l, MMA rounds its copy
#pragma unroll
            for (int nt = 0; nt < 8; nt++) {
                float p0 = __expf(sf[nt][0]);
                float p1 = __expf(sf[nt][1]);
                float p2 = __expf(sf[nt][2]);
                float p3 = __expf(sf[nt][3]);
                sf[nt][0] = p0; sf[nt][1] = p1; sf[nt][2] = p2; sf[nt][3] = p3;
                l0 += p0 + p1; l1 += p2 + p3;
            }

            // O += P @ V (C-frag -> A-frag relayout via quad shuffles)
#pragma unroll
            for (int kk = 0; kk < 8; kk++) {
                const float x0 = __shfl_sync(0xffffffffu, sf[kk][0], srcA);
                const float x1 = __shfl_sync(0xffffffffu, sf[kk][1], srcA);
                const float x2 = __shfl_sync(0xffffffffu, sf[kk][2], srcA);
                const float x3 = __shfl_sync(0xffffffffu, sf[kk][3], srcA);
                const float z0 = __shfl_sync(0xffffffffu, sf[kk][0], srcB);
                const float z1 = __shfl_sync(0xffffffffu, sf[kk][1], srcB);
                const float z2 = __shfl_sync(0xffffffffu, sf[kk][2], srcB);
                const float z3 = __shfl_sync(0xffffffffu, sf[kk][3], srcB);
                unsigned a[4];
                a[0] = __float_as_uint((tig & 1) ? x1 : x0);
                a[1] = __float_as_uint((tig & 1) ? x3 : x2);
                a[2] = __float_as_uint((tig & 1) ? z1 : z0);
                a[3] = __float_as_uint((tig & 1) ? z3 : z2);
#pragma unroll
                for (int nt = 0; nt < 8; nt++) {
                    unsigned bb[2];
                    bb[0] = __float_as_uint(vs[(kk*8 + tig    )*VS_STRIDE + nt*8 + g]);
                    bb[1] = __float_as_uint(vs[(kk*8 + tig + 4)*VS_STRIDE + nt*8 + g]);
                    mma_tf32(of[nt], a, bb);
                }
            }
        }

        __syncthreads();   // all warps done reading slot buf before refill
        buf ^= 1;
    }
#undef ATT_COPY

    l0 += __shfl_xor_sync(0xffffffffu, l0, 1);
    l0 += __shfl_xor_sync(0xffffffffu, l0, 2);
    l1 += __shfl_xor_sync(0xffffffffu, l1, 1);
    l1 += __shfl_xor_sync(0xffffffffu, l1, 2);
    const float inv0 = 1.f / l0, inv1 = 1.f / l1;

    float* yr0 = y + (size_t)(b*Tc + q0*256 + m0 + g) * Dc + h*DHc;
    float* yr1 = yr0 + (size_t)8 * Dc;
#pragma unroll
    for (int nt = 0; nt < 8; nt++) {
        float2 v0 = make_float2(of[nt][0]*inv0, of[nt][1]*inv0);
        float2 v1 = make_float2(of[nt][2]*inv1, of[nt][3]*inv1);
        *reinterpret_cast<float2*>(yr0 + nt*8 + 2*tig) = v0;
        *reinterpret_cast<float2*>(yr1 + nt*8 + 2*tig) = v1;
    }
}

extern "C" void kernel_launch(void* const* d_in, const int* in_sizes, int n_in,
                              void* d_out, int out_size) {
    const float* x      = (const float*)d_in[0];
    const float* W_qkv  = (const float*)d_in[1];
    const float* W_qlsr = (const float*)d_in[2];
    const float* W_klsr = (const float*)d_in[3];
    const float* core   = (const float*)d_in[4];
    const float* W_o    = (const float*)d_in[5];
    float* out = (float*)d_out;

    float* d_wc; cudaGetSymbolAddress((void**)&d_wc, g_wc);
    float* d_lr; cudaGetSymbolAddress((void**)&d_lr, g_lr);
    float* d_y;  cudaGetSymbolAddress((void**)&d_y,  g_y);

    cudaFuncSetAttribute(attn_tc_kernel, cudaFuncAttributeMaxDynamicSharedMemorySize, ATTN_SMEM);

    // 0) fold LSR weights + copy V weights (merged, rounded)
    prep_kernel<<<dim3(8, 16, 2), 256>>>(W_qkv, W_qlsr, W_klsr, core, d_wc);

    // 1) [ql|kl|v] = x @ wc, output rounded to tf32
    gemm_tf32_kernel<true><<<dim3(LRW/128, Mrows/128), 256>>>(x, d_wc, d_lr, Mrows, LRW, Dc, LRW);

    // 2) causal flash attention (512 thr, 256 q-rows/block) -> g_y
    attn_tc_kernel<<<Bc*Hc*8, 512, ATTN_SMEM>>>(d_y);

    // 3) out = y @ W_o (full fp32 output)
    gemm_tf32_kernel<false><<<dim3(Dc/128, Mrows/128), 256>>>(d_y, W_o, out, Mrows, Dc, Dc, Dc);
}

// round 16
// speedup vs baseline: 1.1462x; 1.1462x over previous
#include <cuda_runtime.h>
#include <cuda_bf16.h>
#include <math.h>

// Problem constants
#define Bc 2
#define Tc 2048
#define Dc 1024
#define Hc 16
#define DHc 64
#define Rc 32
#define TDc (3*Dc)        // 3072
#define Mrows (Bc*Tc)     // 4096
#define LRW 2048          // combined row: [ql(512) | kl(512) | v(1024)]

// Scratch (device globals — no allocation allowed)
__device__ float g_wc[(size_t)Dc*LRW];        // folded weights (tf32-rounded)
__device__ float g_lr[(size_t)Mrows*LRW];     // [ql | kl | v] per row (tf32-rounded by GEMM1 epilogue)
__device__ float g_y [(size_t)Mrows*Dc];      // attention output (fp32)

__device__ __forceinline__ float cvt_tf32(float x) {
    float r;
    asm("cvt.rna.tf32.f32 %0, %1;" : "=f"(r) : "f"(x));
    return r;
}

__device__ __forceinline__ void mma_tf32(float* c, const unsigned* a, const unsigned* b) {
    asm volatile(
        "mma.sync.aligned.m16n8k8.row.col.f32.tf32.tf32.f32 "
        "{%0,%1,%2,%3},{%4,%5,%6,%7},{%8,%9},{%0,%1,%2,%3};"
        : "+f"(c[0]), "+f"(c[1]), "+f"(c[2]), "+f"(c[3])
        : "r"(a[0]), "r"(a[1]), "r"(a[2]), "r"(a[3]), "r"(b[0]), "r"(b[1]));
}

__device__ __forceinline__ void cp16(void* smem, const void* gmem) {
    unsigned saddr = (unsigned)__cvta_generic_to_shared(smem);
    asm volatile("cp.async.ca.shared.global [%0], [%1], 16;" :: "r"(saddr), "l"(gmem));
}
__device__ __forceinline__ void cp_commit() {
    asm volatile("cp.async.commit_group;");
}
template<int N>
__device__ __forceinline__ void cp_wait() {
    asm volatile("cp.async.wait_group %0;" :: "n"(N));
}

// ---------------------------------------------------------------------------
// Weight folding + V copy merged (z=0: fold q/k LSR; z=1: copy V weights).
// ---------------------------------------------------------------------------
__global__ __launch_bounds__(256) void prep_kernel(const float* __restrict__ Wqkv,
                                                   const float* __restrict__ Wql,
                                                   const float* __restrict__ Wkl,
                                                   const float* __restrict__ core,
                                                   float* __restrict__ wc) {
    if (blockIdx.z == 1) {
        const int id = blockIdx.y * 8 + blockIdx.x;   // 0..127
        const int tid = threadIdx.x;
#pragma unroll
        for (int rr = 0; rr < 8; rr++) {
            const int row = id * 8 + rr;
            const int c = tid * 4;
            float4 v = *reinterpret_cast<const float4*>(&Wqkv[(size_t)row*TDc + 2*Dc + c]);
            v.x = cvt_tf32(v.x); v.y = cvt_tf32(v.y);
            v.z = cvt_tf32(v.z); v.w = cvt_tf32(v.w);
            *reinterpret_cast<float4*>(&wc[(size_t)row*LRW + 1024 + c]) = v;
        }
        return;
    }

    const int h  = blockIdx.y;
    const int d0 = blockIdx.x * 128;
    __shared__ float Wq[DHc*Rc], Wk[DHc*Rc];
    __shared__ float Aq[32*DHc], Ak[32*DHc];
    __shared__ float cs[Rc];
    const int tid = threadIdx.x;
    for (int i = tid; i < DHc*Rc; i += 256) {
        Wq[i] = Wql[(size_t)h*DHc*Rc + i];
        Wk[i] = Wkl[(size_t)h*DHc*Rc + i];
    }
    if (tid < Rc) cs[tid] = core[h*Rc + tid] * 0.17677669529663687f;
    __syncthreads();

    for (int c = 0; c < 4; c++) {
        const int dbase = d0 + c*32;
        for (int f = tid; f < 512; f += 256) {
            const int row = f >> 4, cc = (f & 15) << 2;
            float4 va = *reinterpret_cast<const float4*>(&Wqkv[(size_t)(dbase+row)*TDc + h*DHc + cc]);
            *reinterpret_cast<float4*>(&Aq[row*DHc + cc]) = va;
            float4 vb = *reinterpret_cast<const float4*>(&Wqkv[(size_t)(dbase+row)*TDc + Dc + h*DHc + cc]);
            *reinterpret_cast<float4*>(&Ak[row*DHc + cc]) = vb;
        }
        __syncthreads();
        const int r = tid & 31, i0 = tid >> 5;
#pragma unroll
        for (int ii = 0; ii < 4; ii++) {
            const int i = i0*4 + ii;
            float sq = 0.f, sk = 0.f;
#pragma unroll
            for (int dh = 0; dh < DHc; dh++) {
                sq = fmaf(Aq[i*DHc + dh], Wq[dh*Rc + r], sq);
                sk = fmaf(Ak[i*DHc + dh], Wk[dh*Rc + r], sk);
            }
            wc[(size_t)(dbase+i)*LRW + h*Rc + r]       = cvt_tf32(sq * cs[r]);
            wc[(size_t)(dbase+i)*LRW + 512 + h*Rc + r] = cvt_tf32(sk);
        }
        __syncthreads();
    }
}

// ---------------------------------------------------------------------------
// TF32 tensor-core GEMM (unchanged proven config: 256 threads, 8 warps,
// 64x32 warp tiles, 2-stage cp.async, 2 CTAs/SM).
// ---------------------------------------------------------------------------
template<bool ROUNDC>
__global__ __launch_bounds__(256, 2) void gemm_tf32_kernel(const float* __restrict__ A,
                                                           const float* __restrict__ B,
                                                           float* __restrict__ C,
                                                           int M, int N, int K, int ldb) {
    __shared__ __align__(16) float As[2][128][20];
    __shared__ __align__(16) float Bs[2][16][136];

    const int tid = threadIdx.x;
    const int warp = tid >> 5, lane = tid & 31;
    const int g = lane >> 2, tig = lane & 3;
    const int wm = warp >> 2;
    const int wn = warp & 3;

    const int c0 = tid * 2;
    const int aRow0 = c0 >> 2,       aKc0 = (c0 & 3) << 2;
    const int aRow1 = (c0+1) >> 2,   aKc1 = ((c0+1) & 3) << 2;
    const int bKr0 = c0 >> 5,        bNc0 = (c0 & 31) << 2;
    const int bKr1 = (c0+1) >> 5,    bNc1 = ((c0+1) & 31) << 2;

    const float* Ab = A + (size_t)blockIdx.y * 128 * K;
    const float* Bb = B + (size_t)blockIdx.x * 128;

    float acc[4][4][4];
#pragma unroll
    for (int i = 0; i < 4; i++)
#pragma unroll
        for (int j = 0; j < 4; j++)
#pragma unroll
            for (int e = 0; e < 4; e++) acc[i][j][e] = 0.f;

    const int nK = K >> 4;

    cp16(&As[0][aRow0][aKc0], &Ab[(size_t)aRow0 * K + aKc0]);
    cp16(&As[0][aRow1][aKc1], &Ab[(size_t)aRow1 * K + aKc1]);
    cp16(&Bs[0][bKr0][bNc0], &Bb[(size_t)bKr0 * ldb + bNc0]);
    cp16(&Bs[0][bKr1][bNc1], &Bb[(size_t)bKr1 * ldb + bNc1]);
    cp_commit();

    int buf = 0;
    for (int kt = 0; kt < nK; kt++) {
        const bool more = (kt + 1 < nK);
        if (more) {
            const int k0 = (kt + 1) << 4;
            const int nb = buf ^ 1;
            cp16(&As[nb][aRow0][aKc0], &Ab[(size_t)aRow0 * K + k0 + aKc0]);
            cp16(&As[nb][aRow1][aKc1], &Ab[(size_t)aRow1 * K + k0 + aKc1]);
            cp16(&Bs[nb][bKr0][bNc0], &Bb[(size_t)(k0 + bKr0) * ldb + bNc0]);
            cp16(&Bs[nb][bKr1][bNc1], &Bb[(size_t)(k0 + bKr1) * ldb + bNc1]);
            cp_commit();
            cp_wait<1>();
        } else {
            cp_wait<0>();
        }
        __syncthreads();

#pragma unroll
        for (int ks = 0; ks < 16; ks += 8) {
            unsigned afr[4][4], bfr[4][2];
#pragma unroll
            for (int im = 0; im < 4; im++) {
                const int m0 = wm * 64 + im * 16;
                afr[im][0] = __float_as_uint(cvt_tf32(As[buf][m0 + g     ][ks + tig    ]));
                afr[im][1] = __float_as_uint(cvt_tf32(As[buf][m0 + g + 8 ][ks + tig    ]));
                afr[im][2] = __float_as_uint(cvt_tf32(As[buf][m0 + g     ][ks + tig + 4]));
                afr[im][3] = __float_as_uint(cvt_tf32(As[buf][m0 + g + 8 ][ks + tig + 4]));
            }
#pragma unroll
            for (int in_ = 0; in_ < 4; in_++) {
                const int n0 = wn * 32 + in_ * 8;
                bfr[in_][0] = __float_as_uint(cvt_tf32(Bs[buf][ks + tig    ][n0 + g]));
                bfr[in_][1] = __float_as_uint(cvt_tf32(Bs[buf][ks + tig + 4][n0 + g]));
            }
#pragma unroll
            for (int im = 0; im < 4; im++)
#pragma unroll
                for (int in_ = 0; in_ < 4; in_++)
                    mma_tf32(acc[im][in_], afr[im], bfr[in_]);
        }
        __syncthreads();
        buf ^= 1;
    }

#pragma unroll
    for (int im = 0; im < 4; im++) {
        const size_t row0 = (size_t)blockIdx.y * 128 + wm * 64 + im * 16 + g;
#pragma unroll
        for (int in_ = 0; in_ < 4; in_++) {
            const size_t col = (size_t)blockIdx.x * 128 + wn * 32 + in_ * 8 + tig * 2;
            float2 v0, v1;
            if (ROUNDC) {
                v0 = make_float2(cvt_tf32(acc[im][in_][0]), cvt_tf32(acc[im][in_][1]));
                v1 = make_float2(cvt_tf32(acc[im][in_][2]), cvt_tf32(acc[im][in_][3]));
            } else {
                v0 = make_float2(acc[im][in_][0], acc[im][in_][1]);
                v1 = make_float2(acc[im][in_][2], acc[im][in_][3]);
            }
            *reinterpret_cast<float2*>(&C[row0 * N + col])       = v0;
            *reinterpret_cast<float2*>(&C[(row0 + 8) * N + col]) = v1;
        }
    }
}

// ---------------------------------------------------------------------------
// Tensor-core flash attention (R14 config: 256 threads, 128 q-rows, 64-key
// cp.async double-buffered tiles, no online softmax, p fp32), with GLOBAL
// heavy-first block ordering: wave 1 = heaviest causal tiles chip-wide.
// ---------------------------------------------------------------------------
#define KLS_STRIDE 36
#define VS_STRIDE  72
#define KT 64
#define KLS_TILE (KT*KLS_STRIDE)   // 2304 floats
#define VS_TILE  (KT*VS_STRIDE)    // 4608 floats
#define ATTN_SMEM ((2*(KLS_TILE + VS_TILE)) * 4)   // 55296 B

__global__ __launch_bounds__(256, 2) void attn_tc_kernel(float* __restrict__ y) {
    extern __shared__ __align__(16) float asm_[];
    float* klsB = asm_;                  // [2][64][36]
    float* vsB  = asm_ + 2*KLS_TILE;     // [2][64][72]

    // GLOBAL heavy-first: blocks 0..31 are qt=15 (all b,h), then qt=14, ...
    const int blk = blockIdx.x;
    const int qt = 15 - (blk >> 5);
    const int bh = blk & 31;
    const int h  = bh & 15;
    const int b  = bh >> 4;
    const int tid  = threadIdx.x;
    const int warp = tid >> 5, lane = tid & 31;
    const int g = lane >> 2, tig = lane & 3;
    const int m0 = warp * 16;

    const float* klg = g_lr + (size_t)(b*Tc) * LRW + 512 + h*Rc;
    const float* vg  = g_lr + (size_t)(b*Tc) * LRW + 1024 + h*DHc;

    // preload ql A-fragments (already tf32-rounded in memory)
    unsigned aq[4][4];
    {
        const float* qlp = g_lr + (size_t)(b*Tc + qt*128 + m0) * LRW + h*Rc;
#pragma unroll
        for (int ks = 0; ks < 4; ks++) {
            aq[ks][0] = __float_as_uint(qlp[(size_t)(g    )*LRW + ks*8 + tig    ]);
            aq[ks][1] = __float_as_uint(qlp[(size_t)(g + 8)*LRW + ks*8 + tig    ]);
            aq[ks][2] = __float_as_uint(qlp[(size_t)(g    )*LRW + ks*8 + tig + 4]);
            aq[ks][3] = __float_as_uint(qlp[(size_t)(g + 8)*LRW + ks*8 + tig + 4]);
        }
    }

    float of[8][4];
#pragma unroll
    for (int nt = 0; nt < 8; nt++)
#pragma unroll
        for (int e = 0; e < 4; e++) of[nt][e] = 0.f;
    float l0 = 0.f, l1 = 0.f;

    const unsigned srcA = (lane & ~3u) | (unsigned)(tig >> 1);
    const unsigned srcB = srcA + 2u;

#define ATT_COPY(s, kt)                                                                   \
    do {                                                                                  \
        float* kls_ = klsB + (s)*KLS_TILE;                                                \
        float* vs_  = vsB  + (s)*VS_TILE;                                                 \
        _Pragma("unroll")                                                                 \
        for (int i = 0; i < 2; i++) {                                                     \
            const int f = tid + i*256;                                                    \
            const int key = f >> 3, r0 = (f & 7) << 2;                                    \
            cp16(&kls_[key*KLS_STRIDE + r0], klg + (size_t)((kt)*KT + key)*LRW + r0);     \
        }                                                                                 \
        _Pragma("unroll")                                                                 \
        for (int i = 0; i < 4; i++) {                                                     \
            const int f = tid + i*256;                                                    \
            const int key = f >> 4, j = (f & 15) << 2;                                    \
            cp16(&vs_[key*VS_STRIDE + j], vg + (size_t)((kt)*KT + key)*LRW + j);          \
        }                                                                                 \
        cp_commit();                                                                      \
    } while (0)

    const int ktMax = 2*qt + 1;
    ATT_COPY(0, 0);

    int buf = 0;
    for (int kt = 0; kt <= ktMax; kt++) {
        if (kt < ktMax) {
            ATT_COPY(buf ^ 1, kt + 1);
            cp_wait<1>();
        } else {
            cp_wait<0>();
        }
        __syncthreads();   // tile kt visible in slot buf

        const bool masked = (kt >= 2*qt);
        const int cbase = (kt - 2*qt) * KT;
        const bool skip = masked && ((m0 + 15) < cbase);

        if (!skip) {
            const float* kls = klsB + buf*KLS_TILE;
            const float* vs  = vsB  + buf*VS_TILE;

            // S = ql @ kl^T  (16 x 64)
            float sf[8][4];
#pragma unroll
            for (int nt = 0; nt < 8; nt++) {
#pragma unroll
                for (int e = 0; e < 4; e++) sf[nt][e] = 0.f;
#pragma unroll
                for (int ks = 0; ks < 4; ks++) {
                    unsigned bb[2];
                    bb[0] = __float_as_uint(kls[(nt*8 + g)*KLS_STRIDE + ks*8 + tig    ]);
                    bb[1] = __float_as_uint(kls[(nt*8 + g)*KLS_STRIDE + ks*8 + tig + 4]);
                    mma_tf32(sf[nt], aq[ks], bb);
                }
            }

            if (masked) {
                const int r0l = m0 + g, r1l = r0l + 8;
#pragma unroll
                for (int nt = 0; nt < 8; nt++) {
                    const int c = cbase + nt*8 + 2*tig;
                    if (c     > r0l) sf[nt][0] = -1e30f;
                    if (c + 1 > r0l) sf[nt][1] = -1e30f;
                    if (c     > r1l) sf[nt][2] = -1e30f;
                    if (c + 1 > r1l) sf[nt][3] = -1e30f;
                }
            }

            // p = exp(s) (fixed max 0); fp32 p feeds l, MMA rounds its copy
#pragma unroll
            for (int nt = 0; nt < 8; nt++) {
                float p0 = __expf(sf[nt][0]);
                float p1 = __expf(sf[nt][1]);
                float p2 = __expf(sf[nt][2]);
                float p3 = __expf(sf[nt][3]);
                sf[nt][0] = p0; sf[nt][1] = p1; sf[nt][2] = p2; sf[nt][3] = p3;
                l0 += p0 + p1; l1 += p2 + p3;
            }

            // O += P @ V (C-frag -> A-frag relayout via quad shuffles)
#pragma unroll
            for (int kk = 0; kk < 8; kk++) {
                const float x0 = __shfl_sync(0xffffffffu, sf[kk][0], srcA);
                const float x1 = __shfl_sync(0xffffffffu, sf[kk][1], srcA);
                const float x2 = __shfl_sync(0xffffffffu, sf[kk][2], srcA);
                const float x3 = __shfl_sync(0xffffffffu, sf[kk][3], srcA);
                const float z0 = __shfl_sync(0xffffffffu, sf[kk][0], srcB);
                const float z1 = __shfl_sync(0xffffffffu, sf[kk][1], srcB);
                const float z2 = __shfl_sync(0xffffffffu, sf[kk][2], srcB);
                const float z3 = __shfl_sync(0xffffffffu, sf[kk][3], srcB);
                unsigned a[4];
                a[0] = __float_as_uint((tig & 1) ? x1 : x0);
                a[1] = __float_as_uint((tig & 1) ? x3 : x2);
                a[2] = __float_as_uint((tig & 1) ? z1 : z0);
                a[3] = __float_as_uint((tig & 1) ? z3 : z2);
#pragma unroll
                for (int nt = 0; nt < 8; nt++) {
                    unsigned bb[2];
                    bb[0] = __float_as_uint(vs[(kk*8 + tig    )*VS_STRIDE + nt*8 + g]);
                    bb[1] = __float_as_uint(vs[(kk*8 + tig + 4)*VS_STRIDE + nt*8 + g]);
                    mma_tf32(of[nt], a, bb);
                }
            }
        }

        __syncthreads();   // all warps done reading slot buf before refill
        buf ^= 1;
    }
#undef ATT_COPY

    l0 += __shfl_xor_sync(0xffffffffu, l0, 1);
    l0 += __shfl_xor_sync(0xffffffffu, l0, 2);
    l1 += __shfl_xor_sync(0xffffffffu, l1, 1);
    l1 += __shfl_xor_sync(0xffffffffu, l1, 2);
    const float inv0 = 1.f / l0, inv1 = 1.f / l1;

    float* yr0 = y + (size_t)(b*Tc + qt*128 + m0 + g) * Dc + h*DHc;
    float* yr1 = yr0 + (size_t)8 * Dc;
#pragma unroll
    for (int nt = 0; nt < 8; nt++) {
        float2 v0 = make_float2(of[nt][0]*inv0, of[nt][1]*inv0);
        float2 v1 = make_float2(of[nt][2]*inv1, of[nt][3]*inv1);
        *reinterpret_cast<float2*>(yr0 + nt*8 + 2*tig) = v0;
        *reinterpret_cast<float2*>(yr1 + nt*8 + 2*tig) = v1;
    }
}

extern "C" void kernel_launch(void* const* d_in, const int* in_sizes, int n_in,
                              void* d_out, int out_size) {
    const float* x      = (const float*)d_in[0];
    const float* W_qkv  = (const float*)d_in[1];
    const float* W_qlsr = (const float*)d_in[2];
    const float* W_klsr = (const float*)d_in[3];
    const float* core   = (const float*)d_in[4];
    const float* W_o    = (const float*)d_in[5];
    float* out = (float*)d_out;

    float* d_wc; cudaGetSymbolAddress((void**)&d_wc, g_wc);
    float* d_lr; cudaGetSymbolAddress((void**)&d_lr, g_lr);
    float* d_y;  cudaGetSymbolAddress((void**)&d_y,  g_y);

    cudaFuncSetAttribute(attn_tc_kernel, cudaFuncAttributeMaxDynamicSharedMemorySize, ATTN_SMEM);

    // 0) fold LSR weights + copy V weights (merged, rounded)
    prep_kernel<<<dim3(8, 16, 2), 256>>>(W_qkv, W_qlsr, W_klsr, core, d_wc);

    // 1) [ql|kl|v] = x @ wc, output rounded to tf32
    gemm_tf32_kernel<true><<<dim3(LRW/128, Mrows/128), 256>>>(x, d_wc, d_lr, Mrows, LRW, Dc, LRW);

    // 2) causal flash attention (global heavy-first schedule) -> g_y
    attn_tc_kernel<<<Bc*Hc*(Tc/128), 256, ATTN_SMEM>>>(d_y);

    // 3) out = y @ W_o (full fp32 output)
    gemm_tf32_kernel<false><<<dim3(Dc/128, Mrows/128), 256>>>(d_y, W_o, out, Mrows, Dc, Dc, Dc);
}